// round 15
// baseline (speedup 1.0000x reference)
#include <cuda_runtime.h>
#include <cuda_fp16.h>

#define NMAX 100000
#define EMAX 1600000
#define HID 64
#define SLOTS 96   // ELL slots per node; P(Poisson(16) >= 96) ~ 1e-37

// ---------------- packed f32x2 helpers (sm_103a dual-fp32 pipe) ----------------
__device__ __forceinline__ unsigned long long pack2(float lo, float hi) {
    unsigned long long r;
    asm("mov.b64 %0, {%1, %2};" : "=l"(r) : "f"(lo), "f"(hi));
    return r;
}
__device__ __forceinline__ float2 unpack2(unsigned long long v) {
    float lo, hi;
    asm("mov.b64 {%0, %1}, %2;" : "=f"(lo), "=f"(hi) : "l"(v));
    return make_float2(lo, hi);
}
__device__ __forceinline__ unsigned long long fma2(unsigned long long a,
                                                   unsigned long long b,
                                                   unsigned long long c) {
    unsigned long long d;
    asm("fma.rn.f32x2 %0, %1, %2, %3;" : "=l"(d) : "l"(a), "l"(b), "l"(c));
    return d;
}

// ---------------- scratch (device globals: allocation-free rule) ----------------
__device__ int    g_deg[NMAX];                       // in-degree; atomic cursor during scatter
__device__ int    g_col[(size_t)NMAX * SLOTS];       // ELL adjacency (src ids PRE-SCALED <<4)
__device__ float  g_norm[NMAX];
__device__ __half g_h1[(size_t)NMAX * HID];          // lin1 out (fp16 gather table)
__device__ float  g_mid[(size_t)NMAX * HID];         // agg1 out (fp32, lin2 input)
__device__ __half g_h2[(size_t)NMAX * HID];          // lin2 out (fp16 gather table)
__device__ float4 g_pq[NMAX];

// ---------------- FUSED: lin1 (half-row per thread, f32x2) + ELL scatter ----------------
__global__ __launch_bounds__(256) void fused_lin1_scatter_kernel(
    const float* __restrict__ x, const float* __restrict__ W,
    const float* __restrict__ b,
    const int* __restrict__ src, const int* __restrict__ dst,
    __half* __restrict__ out, int n, int e, int nbLin)
{
    __shared__ float Ws[128 * HID];   // 32 KB
    __shared__ float bs[HID];

    if (blockIdx.x < nbLin) {
        // -------- GEMM branch: 2 threads per row, 32 cols each, packed f32x2 --------
        for (int i = threadIdx.x; i < (128 * HID) / 4; i += 256)
            ((float4*)Ws)[i] = ((const float4*)W)[i];
        if (threadIdx.x < HID) bs[threadIdx.x] = b[threadIdx.x];
        __syncthreads();

        int gid = blockIdx.x * 256 + threadIdx.x;
        int row = gid >> 1;
        int half = gid & 1;
        if (row >= n) return;

        unsigned long long acc2[16];
#pragma unroll
        for (int c = 0; c < 16; c++) acc2[c] = 0ull;

        const float4* xr = (const float4*)(x + (size_t)row * 128);
        int cbase = half * 32;
#pragma unroll
        for (int k4 = 0; k4 < 32; k4++) {
            float4 xv = xr[k4];
            float xk[4] = {xv.x, xv.y, xv.z, xv.w};
#pragma unroll
            for (int kk = 0; kk < 4; kk++) {
                unsigned long long xp = pack2(xk[kk], xk[kk]);
                const ulonglong2* wr =
                    (const ulonglong2*)(Ws + (k4 * 4 + kk) * HID + cbase);
#pragma unroll
                for (int c = 0; c < 8; c++) {
                    ulonglong2 w = wr[c];
                    acc2[2 * c + 0] = fma2(xp, w.x, acc2[2 * c + 0]);
                    acc2[2 * c + 1] = fma2(xp, w.y, acc2[2 * c + 1]);
                }
            }
        }
        __half2 hv[16];
#pragma unroll
        for (int c = 0; c < 16; c++) {
            float2 v = unpack2(acc2[c]);
            hv[c] = __floats2half2_rn(v.x + bs[cbase + 2 * c],
                                      v.y + bs[cbase + 2 * c + 1]);
        }
        uint4* o = (uint4*)(out + (size_t)row * HID + cbase);
        o[0] = ((uint4*)hv)[0];
        o[1] = ((uint4*)hv)[1];
        o[2] = ((uint4*)hv)[2];
        o[3] = ((uint4*)hv)[3];
    } else {
        // -------- ELL scatter branch, 8 edges per thread (store src<<4: uint2-row idx) --------
        int bid = blockIdx.x - nbLin;
        int i0 = (bid * 256 + threadIdx.x) * 8;
        if (i0 >= e) return;
        if (i0 + 8 <= e) {
            int4 sa = *(const int4*)(src + i0);
            int4 sb = *(const int4*)(src + i0 + 4);
            int4 da = *(const int4*)(dst + i0);
            int4 db = *(const int4*)(dst + i0 + 4);
            int p0 = atomicAdd(&g_deg[da.x], 1);
            int p1 = atomicAdd(&g_deg[da.y], 1);
            int p2 = atomicAdd(&g_deg[da.z], 1);
            int p3 = atomicAdd(&g_deg[da.w], 1);
            int p4 = atomicAdd(&g_deg[db.x], 1);
            int p5 = atomicAdd(&g_deg[db.y], 1);
            int p6 = atomicAdd(&g_deg[db.z], 1);
            int p7 = atomicAdd(&g_deg[db.w], 1);
            if (p0 < SLOTS) g_col[(size_t)da.x * SLOTS + p0] = sa.x << 4;
            if (p1 < SLOTS) g_col[(size_t)da.y * SLOTS + p1] = sa.y << 4;
            if (p2 < SLOTS) g_col[(size_t)da.z * SLOTS + p2] = sa.z << 4;
            if (p3 < SLOTS) g_col[(size_t)da.w * SLOTS + p3] = sa.w << 4;
            if (p4 < SLOTS) g_col[(size_t)db.x * SLOTS + p4] = sb.x << 4;
            if (p5 < SLOTS) g_col[(size_t)db.y * SLOTS + p5] = sb.y << 4;
            if (p6 < SLOTS) g_col[(size_t)db.z * SLOTS + p6] = sb.z << 4;
            if (p7 < SLOTS) g_col[(size_t)db.w * SLOTS + p7] = sb.w << 4;
        } else {
            for (int i = i0; i < e; i++) {
                int d = dst[i];
                int p = atomicAdd(&g_deg[d], 1);
                if (p < SLOTS) g_col[(size_t)d * SLOTS + p] = src[i] << 4;
            }
        }
    }
}

// ---------------- agg1: 2 nodes/warp (half-warp each), uint2 gathers, unroll 8 ----------------
// + in-half-warp distinct count (match_any on half mask) + norm + relu
__global__ void agg1_kernel(const __half* __restrict__ h,
                            const float* __restrict__ wpan,
                            float* __restrict__ out, int n) {
    int gw = (blockIdx.x * blockDim.x + threadIdx.x) >> 5;
    int lane = threadIdx.x & 31;
    int half = lane >> 4;
    int l16 = lane & 15;
    int node = gw * 2 + half;
    if (node >= n) return;
    unsigned hmask = half ? 0xFFFF0000u : 0x0000FFFFu;

    int deg = g_deg[node];
    if (deg > SLOTS) deg = SLOTS;
    const int* colp = g_col + (size_t)node * SLOTS;
    int nodeS = node << 4;   // scaled self id (uint2-row index)

    // prefetch self row early (overlaps dedup latency)
    const uint2* hb = (const uint2*)h + l16;   // lane-offset base (uint2 granularity)
    uint2 sv = hb[nodeS];

    // ---- distinct in-neighbor count (coalesce semantics), half-warp chunks of 16 ----
    int cnt = 1;  // diagonal
    for (int c0 = 0; c0 < deg; c0 += 16) {
        int idx = c0 + l16;
        int v = (idx < deg) ? colp[idx] : (-1 - lane);  // unique negatives never match
        bool valid = (idx < deg) && (v != nodeS);
        unsigned m = __match_any_sync(hmask, v);
        bool lead = valid && ((m & ((1u << lane) - 1u)) == 0u);
        if (lead && c0 > 0) {
            for (int j = 0; j < c0; j++)
                if (colp[j] == v) { lead = false; break; }
        }
        cnt += __popc(__ballot_sync(hmask, lead));
    }
    float nm = 1.0f / (float)cnt;
    if (l16 == 0) g_norm[node] = nm;

    // ---- gather-reduce: unroll 8 (two int4 index loads), 4-deep HADD2 trees + fp32 add ----
    float ax = 0.f, ay = 0.f, az = 0.f, aw = 0.f;
    int j = 0;
    for (; j + 7 < deg; j += 8) {
        int4 ca = *(const int4*)(colp + j);
        int4 cb = *(const int4*)(colp + j + 4);
        uint2 v0 = hb[ca.x], v1 = hb[ca.y], v2 = hb[ca.z], v3 = hb[ca.w];
        uint2 v4 = hb[cb.x], v5 = hb[cb.y], v6 = hb[cb.z], v7 = hb[cb.w];
        __half2 sa = __hadd2(__hadd2(*(__half2*)&v0.x, *(__half2*)&v1.x),
                             __hadd2(*(__half2*)&v2.x, *(__half2*)&v3.x));
        __half2 sb = __hadd2(__hadd2(*(__half2*)&v0.y, *(__half2*)&v1.y),
                             __hadd2(*(__half2*)&v2.y, *(__half2*)&v3.y));
        __half2 sc = __hadd2(__hadd2(*(__half2*)&v4.x, *(__half2*)&v5.x),
                             __hadd2(*(__half2*)&v6.x, *(__half2*)&v7.x));
        __half2 sd = __hadd2(__hadd2(*(__half2*)&v4.y, *(__half2*)&v5.y),
                             __hadd2(*(__half2*)&v6.y, *(__half2*)&v7.y));
        float2 fa = __half22float2(sa), fb = __half22float2(sb);
        float2 fc = __half22float2(sc), fd = __half22float2(sd);
        ax += fa.x + fc.x; ay += fa.y + fc.y;
        az += fb.x + fd.x; aw += fb.y + fd.y;
    }
    for (; j + 3 < deg; j += 4) {
        int4 c4 = *(const int4*)(colp + j);
        uint2 v0 = hb[c4.x], v1 = hb[c4.y], v2 = hb[c4.z], v3 = hb[c4.w];
        __half2 sa = __hadd2(__hadd2(*(__half2*)&v0.x, *(__half2*)&v1.x),
                             __hadd2(*(__half2*)&v2.x, *(__half2*)&v3.x));
        __half2 sb = __hadd2(__hadd2(*(__half2*)&v0.y, *(__half2*)&v1.y),
                             __hadd2(*(__half2*)&v2.y, *(__half2*)&v3.y));
        float2 fa = __half22float2(sa);
        float2 fb = __half22float2(sb);
        ax += fa.x; ay += fa.y; az += fb.x; aw += fb.y;
    }
    for (; j < deg; j++) {
        uint2 v = hb[colp[j]];
        float2 fa = __half22float2(*(__half2*)&v.x);
        float2 fb = __half22float2(*(__half2*)&v.y);
        ax += fa.x; ay += fa.y; az += fb.x; aw += fb.y;
    }
    float w0 = wpan[0];
    float w01 = w0 * wpan[1];
    float2 ha = __half22float2(*(__half2*)&sv.x);
    float2 hbv = __half22float2(*(__half2*)&sv.y);
    float4 o;
    o.x = fmaxf(nm * (w0 * ha.x + w01 * ax), 0.f);
    o.y = fmaxf(nm * (w0 * ha.y + w01 * ay), 0.f);
    o.z = fmaxf(nm * (w0 * hbv.x + w01 * az), 0.f);
    o.w = fmaxf(nm * (w0 * hbv.y + w01 * aw), 0.f);
    ((float4*)out)[(size_t)node * 16 + l16] = o;
}

// ---------------- layer-2 linear (packed f32x2, 2 threads/row): h2 = fp16( mid @ W2 + b2 ) ----------------
__global__ __launch_bounds__(256) void lin2_kernel(const float* __restrict__ x,
                                                   const float* __restrict__ W,
                                                   const float* __restrict__ b,
                                                   __half* __restrict__ out, int n) {
    __shared__ float Ws[64 * HID];
    __shared__ float bs[HID];
    for (int i = threadIdx.x; i < (64 * HID) / 4; i += blockDim.x)
        ((float4*)Ws)[i] = ((const float4*)W)[i];
    if (threadIdx.x < HID) bs[threadIdx.x] = b[threadIdx.x];
    __syncthreads();

    int gid = blockIdx.x * 256 + threadIdx.x;
    int row = gid >> 1;
    int half = gid & 1;
    if (row >= n) return;
    int cbase = half * 32;

    unsigned long long acc2[16];
#pragma unroll
    for (int c = 0; c < 16; c++) acc2[c] = 0ull;

    const float4* xr = (const float4*)(x + (size_t)row * 64);
#pragma unroll
    for (int k4 = 0; k4 < 16; k4++) {
        float4 xv = xr[k4];
        float xk[4] = {xv.x, xv.y, xv.z, xv.w};
#pragma unroll
        for (int kk = 0; kk < 4; kk++) {
            unsigned long long xp = pack2(xk[kk], xk[kk]);
            const ulonglong2* wr = (const ulonglong2*)(Ws + (k4 * 4 + kk) * HID + cbase);
#pragma unroll
            for (int c = 0; c < 8; c++) {
                ulonglong2 w = wr[c];
                acc2[2 * c + 0] = fma2(xp, w.x, acc2[2 * c + 0]);
                acc2[2 * c + 1] = fma2(xp, w.y, acc2[2 * c + 1]);
            }
        }
    }
    __half2 hv[16];
#pragma unroll
    for (int c = 0; c < 16; c++) {
        float2 v = unpack2(acc2[c]);
        hv[c] = __floats2half2_rn(v.x + bs[cbase + 2 * c],
                                  v.y + bs[cbase + 2 * c + 1]);
    }
    uint4* o = (uint4*)(out + (size_t)row * HID + cbase);
    o[0] = ((uint4*)hv)[0];
    o[1] = ((uint4*)hv)[1];
    o[2] = ((uint4*)hv)[2];
    o[3] = ((uint4*)hv)[3];
}

// ---------------- agg2 + pq: 2 nodes/warp, uint2 gathers, unroll 8, width-16 reduce ----------------
__global__ __launch_bounds__(256) void agg2pq_kernel(const __half* __restrict__ h,
                                                     const float* __restrict__ wpan,
                                                     const float* __restrict__ wc, int n) {
    __shared__ float wcs[256];  // wc [128,2]
    for (int i = threadIdx.x; i < 256; i += blockDim.x) wcs[i] = wc[i];
    __syncthreads();

    int gw = (blockIdx.x * blockDim.x + threadIdx.x) >> 5;
    int lane = threadIdx.x & 31;
    int half = lane >> 4;
    int l16 = lane & 15;
    int node = gw * 2 + half;
    if (node >= n) return;
    unsigned hmask = half ? 0xFFFF0000u : 0x0000FFFFu;

    int deg = g_deg[node];
    if (deg > SLOTS) deg = SLOTS;
    const int* colp = g_col + (size_t)node * SLOTS;

    // prefetch self row + norm early (overlap gather latency)
    const uint2* hb = (const uint2*)h + l16;
    uint2 sv = hb[node << 4];
    float nm = g_norm[node];

    float ax = 0.f, ay = 0.f, az = 0.f, aw = 0.f;
    int j = 0;
    for (; j + 7 < deg; j += 8) {
        int4 ca = *(const int4*)(colp + j);
        int4 cb = *(const int4*)(colp + j + 4);
        uint2 v0 = hb[ca.x], v1 = hb[ca.y], v2 = hb[ca.z], v3 = hb[ca.w];
        uint2 v4 = hb[cb.x], v5 = hb[cb.y], v6 = hb[cb.z], v7 = hb[cb.w];
        __half2 sa = __hadd2(__hadd2(*(__half2*)&v0.x, *(__half2*)&v1.x),
                             __hadd2(*(__half2*)&v2.x, *(__half2*)&v3.x));
        __half2 sb = __hadd2(__hadd2(*(__half2*)&v0.y, *(__half2*)&v1.y),
                             __hadd2(*(__half2*)&v2.y, *(__half2*)&v3.y));
        __half2 sc = __hadd2(__hadd2(*(__half2*)&v4.x, *(__half2*)&v5.x),
                             __hadd2(*(__half2*)&v6.x, *(__half2*)&v7.x));
        __half2 sd = __hadd2(__hadd2(*(__half2*)&v4.y, *(__half2*)&v5.y),
                             __hadd2(*(__half2*)&v6.y, *(__half2*)&v7.y));
        float2 fa = __half22float2(sa), fb = __half22float2(sb);
        float2 fc = __half22float2(sc), fd = __half22float2(sd);
        ax += fa.x + fc.x; ay += fa.y + fc.y;
        az += fb.x + fd.x; aw += fb.y + fd.y;
    }
    for (; j + 3 < deg; j += 4) {
        int4 c4 = *(const int4*)(colp + j);
        uint2 v0 = hb[c4.x], v1 = hb[c4.y], v2 = hb[c4.z], v3 = hb[c4.w];
        __half2 sa = __hadd2(__hadd2(*(__half2*)&v0.x, *(__half2*)&v1.x),
                             __hadd2(*(__half2*)&v2.x, *(__half2*)&v3.x));
        __half2 sb = __hadd2(__hadd2(*(__half2*)&v0.y, *(__half2*)&v1.y),
                             __hadd2(*(__half2*)&v2.y, *(__half2*)&v3.y));
        float2 fa = __half22float2(sa);
        float2 fb = __half22float2(sb);
        ax += fa.x; ay += fa.y; az += fb.x; aw += fb.y;
    }
    for (; j < deg; j++) {
        uint2 v = hb[colp[j]];
        float2 fa = __half22float2(*(__half2*)&v.x);
        float2 fb = __half22float2(*(__half2*)&v.y);
        ax += fa.x; ay += fa.y; az += fb.x; aw += fb.y;
    }
    float w0 = wpan[0];
    float w01 = w0 * wpan[1];
    float2 ha = __half22float2(*(__half2*)&sv.x);
    float2 hbv = __half22float2(*(__half2*)&sv.y);
    float o0 = nm * (w0 * ha.x + w01 * ax);   // h_final[4*l16+0]
    float o1 = nm * (w0 * ha.y + w01 * ay);   // h_final[4*l16+1]
    float o2 = nm * (w0 * hbv.x + w01 * az);  // h_final[4*l16+2]
    float o3 = nm * (w0 * hbv.y + w01 * aw);  // h_final[4*l16+3]

    // classifier halves: lane covers cols c=4*l16..4*l16+3
    int cb4 = 4 * l16;
    float p0 = o0 * wcs[(cb4 + 0) * 2] + o1 * wcs[(cb4 + 1) * 2]
             + o2 * wcs[(cb4 + 2) * 2] + o3 * wcs[(cb4 + 3) * 2];
    float p1 = o0 * wcs[(cb4 + 0) * 2 + 1] + o1 * wcs[(cb4 + 1) * 2 + 1]
             + o2 * wcs[(cb4 + 2) * 2 + 1] + o3 * wcs[(cb4 + 3) * 2 + 1];
    float q0 = o0 * wcs[(64 + cb4 + 0) * 2] + o1 * wcs[(64 + cb4 + 1) * 2]
             + o2 * wcs[(64 + cb4 + 2) * 2] + o3 * wcs[(64 + cb4 + 3) * 2];
    float q1 = o0 * wcs[(64 + cb4 + 0) * 2 + 1] + o1 * wcs[(64 + cb4 + 1) * 2 + 1]
             + o2 * wcs[(64 + cb4 + 2) * 2 + 1] + o3 * wcs[(64 + cb4 + 3) * 2 + 1];
#pragma unroll
    for (int off = 8; off > 0; off >>= 1) {
        p0 += __shfl_down_sync(hmask, p0, off, 16);
        p1 += __shfl_down_sync(hmask, p1, off, 16);
        q0 += __shfl_down_sync(hmask, q0, off, 16);
        q1 += __shfl_down_sync(hmask, q1, off, 16);
    }
    if (l16 == 0) g_pq[node] = make_float4(p0, p1, q0, q1);
}

// ---------------- per-edge output (8 edges/thread) ----------------
__global__ void edge_kernel(const int* __restrict__ src,
                            const int* __restrict__ dst,
                            const float* __restrict__ bc,
                            float* __restrict__ out, int e) {
    int i0 = (blockIdx.x * blockDim.x + threadIdx.x) * 8;
    if (i0 >= e) return;
    float b0 = __ldg(&bc[0]), b1 = __ldg(&bc[1]);
    if (i0 + 8 <= e) {
        int4 sa = *(const int4*)(src + i0);
        int4 sb = *(const int4*)(src + i0 + 4);
        int4 da = *(const int4*)(dst + i0);
        int4 db = *(const int4*)(dst + i0 + 4);
        float4 p0 = g_pq[sa.x], q0 = g_pq[da.x];
        float4 p1 = g_pq[sa.y], q1 = g_pq[da.y];
        float4 p2 = g_pq[sa.z], q2 = g_pq[da.z];
        float4 p3 = g_pq[sa.w], q3 = g_pq[da.w];
        float4 p4 = g_pq[sb.x], q4 = g_pq[db.x];
        float4 p5 = g_pq[sb.y], q5 = g_pq[db.y];
        float4 p6 = g_pq[sb.z], q6 = g_pq[db.z];
        float4 p7 = g_pq[sb.w], q7 = g_pq[db.w];
        float4 o0, o1, o2, o3;
        o0.x = p0.x + q0.z + b0; o0.y = p0.y + q0.w + b1;
        o0.z = p1.x + q1.z + b0; o0.w = p1.y + q1.w + b1;
        o1.x = p2.x + q2.z + b0; o1.y = p2.y + q2.w + b1;
        o1.z = p3.x + q3.z + b0; o1.w = p3.y + q3.w + b1;
        o2.x = p4.x + q4.z + b0; o2.y = p4.y + q4.w + b1;
        o2.z = p5.x + q5.z + b0; o2.w = p5.y + q5.w + b1;
        o3.x = p6.x + q6.z + b0; o3.y = p6.y + q6.w + b1;
        o3.z = p7.x + q7.z + b0; o3.w = p7.y + q7.w + b1;
        float4* op = (float4*)(out + (size_t)i0 * 2);
        op[0] = o0; op[1] = o1; op[2] = o2; op[3] = o3;
    } else {
        for (int i = i0; i < e; i++) {
            float4 ps = g_pq[src[i]];
            float4 qd = g_pq[dst[i]];
            ((float2*)out)[i] = make_float2(ps.x + qd.z + b0, ps.y + qd.w + b1);
        }
    }
}

// ---------------- launch ----------------
extern "C" void kernel_launch(void* const* d_in, const int* in_sizes, int n_in,
                              void* d_out, int out_size) {
    const float* x   = (const float*)d_in[0];
    const int*   ei  = (const int*)d_in[1];
    const float* w1  = (const float*)d_in[2];
    const float* b1  = (const float*)d_in[3];
    const float* p1  = (const float*)d_in[4];  // w1_pan
    const float* w2  = (const float*)d_in[5];
    const float* b2  = (const float*)d_in[6];
    const float* p2  = (const float*)d_in[7];  // w2_pan
    const float* wc  = (const float*)d_in[8];
    const float* bc  = (const float*)d_in[9];
    float* out = (float*)d_out;

    int n = in_sizes[0] / 128;
    int e = in_sizes[1] / 2;
    const int* src = ei;
    const int* dst = ei + e;

    __half* h1 = nullptr; __half* h2 = nullptr; float* mid = nullptr;
    int* degPtr = nullptr;
    cudaGetSymbolAddress((void**)&h1, g_h1);
    cudaGetSymbolAddress((void**)&h2, g_h2);
    cudaGetSymbolAddress((void**)&mid, g_mid);
    cudaGetSymbolAddress((void**)&degPtr, g_deg);

    int ebv8 = (e / 8 + 255) / 256 + 1;       // 8 edges/thread
    int nbLin = (2 * n + 255) / 256;          // half-row lin blocks
    int nwarp2 = (n + 1) / 2;                  // 2 nodes per warp
    int aggBlocks = (nwarp2 * 32 + 255) / 256;

    cudaMemsetAsync(degPtr, 0, (size_t)n * sizeof(int));
    fused_lin1_scatter_kernel<<<nbLin + ebv8, 256>>>(x, w1, b1, src, dst, h1, n, e, nbLin);

    agg1_kernel<<<aggBlocks, 256>>>(h1, p1, mid, n);       // agg1 + distinct/norm + relu
    lin2_kernel<<<nbLin, 256>>>(mid, w2, b2, h2, n);       // layer-2 lin (2 thr/row)
    agg2pq_kernel<<<aggBlocks, 256>>>(h2, p2, wc, n);      // layer-2 agg + pq
    edge_kernel<<<ebv8, 256>>>(src, dst, bc, out, e);
}

// round 16
// speedup vs baseline: 1.0992x; 1.0992x over previous
#include <cuda_runtime.h>
#include <cuda_fp16.h>

#define NMAX 100000
#define EMAX 1600000
#define HID 64
#define SLOTS 96   // ELL slots per node; P(Poisson(16) >= 96) ~ 1e-37

// ---------------- packed f32x2 helpers (sm_103a dual-fp32 pipe) ----------------
__device__ __forceinline__ unsigned long long pack2(float lo, float hi) {
    unsigned long long r;
    asm("mov.b64 %0, {%1, %2};" : "=l"(r) : "f"(lo), "f"(hi));
    return r;
}
__device__ __forceinline__ float2 unpack2(unsigned long long v) {
    float lo, hi;
    asm("mov.b64 {%0, %1}, %2;" : "=f"(lo), "=f"(hi) : "l"(v));
    return make_float2(lo, hi);
}
__device__ __forceinline__ unsigned long long fma2(unsigned long long a,
                                                   unsigned long long b,
                                                   unsigned long long c) {
    unsigned long long d;
    asm("fma.rn.f32x2 %0, %1, %2, %3;" : "=l"(d) : "l"(a), "l"(b), "l"(c));
    return d;
}

// ---------------- scratch (device globals: allocation-free rule) ----------------
__device__ int    g_deg[NMAX];                       // in-degree; atomic cursor during scatter
__device__ int    g_col[(size_t)NMAX * SLOTS];       // ELL adjacency (src ids PRE-SCALED <<4)
__device__ float  g_norm[NMAX];
__device__ __half g_h1[(size_t)NMAX * HID];          // lin1 out (fp16 gather table)
__device__ float  g_mid[(size_t)NMAX * HID];         // agg1 out (fp32, lin2 input)
__device__ __half g_h2[(size_t)NMAX * HID];          // lin2 out (fp16 gather table)
__device__ float4 g_pq[NMAX];

// ---------------- FUSED: lin1 (half-row per thread, f32x2) + ELL scatter ----------------
__global__ __launch_bounds__(256) void fused_lin1_scatter_kernel(
    const float* __restrict__ x, const float* __restrict__ W,
    const float* __restrict__ b,
    const int* __restrict__ src, const int* __restrict__ dst,
    __half* __restrict__ out, int n, int e, int nbLin)
{
    __shared__ float Ws[128 * HID];   // 32 KB
    __shared__ float bs[HID];

    if (blockIdx.x < nbLin) {
        // -------- GEMM branch: 2 threads per row, 32 cols each, packed f32x2 --------
        for (int i = threadIdx.x; i < (128 * HID) / 4; i += 256)
            ((float4*)Ws)[i] = ((const float4*)W)[i];
        if (threadIdx.x < HID) bs[threadIdx.x] = b[threadIdx.x];
        __syncthreads();

        int gid = blockIdx.x * 256 + threadIdx.x;
        int row = gid >> 1;
        int half = gid & 1;
        if (row >= n) return;

        unsigned long long acc2[16];
#pragma unroll
        for (int c = 0; c < 16; c++) acc2[c] = 0ull;

        const float4* xr = (const float4*)(x + (size_t)row * 128);
        int cbase = half * 32;
#pragma unroll
        for (int k4 = 0; k4 < 32; k4++) {
            float4 xv = xr[k4];
            float xk[4] = {xv.x, xv.y, xv.z, xv.w};
#pragma unroll
            for (int kk = 0; kk < 4; kk++) {
                unsigned long long xp = pack2(xk[kk], xk[kk]);
                const ulonglong2* wr =
                    (const ulonglong2*)(Ws + (k4 * 4 + kk) * HID + cbase);
#pragma unroll
                for (int c = 0; c < 8; c++) {
                    ulonglong2 w = wr[c];
                    acc2[2 * c + 0] = fma2(xp, w.x, acc2[2 * c + 0]);
                    acc2[2 * c + 1] = fma2(xp, w.y, acc2[2 * c + 1]);
                }
            }
        }
        __half2 hv[16];
#pragma unroll
        for (int c = 0; c < 16; c++) {
            float2 v = unpack2(acc2[c]);
            hv[c] = __floats2half2_rn(v.x + bs[cbase + 2 * c],
                                      v.y + bs[cbase + 2 * c + 1]);
        }
        uint4* o = (uint4*)(out + (size_t)row * HID + cbase);
        o[0] = ((uint4*)hv)[0];
        o[1] = ((uint4*)hv)[1];
        o[2] = ((uint4*)hv)[2];
        o[3] = ((uint4*)hv)[3];
    } else {
        // -------- ELL scatter branch, 8 edges per thread (store src<<4: uint2-row idx) --------
        int bid = blockIdx.x - nbLin;
        int i0 = (bid * 256 + threadIdx.x) * 8;
        if (i0 >= e) return;
        if (i0 + 8 <= e) {
            int4 sa = *(const int4*)(src + i0);
            int4 sb = *(const int4*)(src + i0 + 4);
            int4 da = *(const int4*)(dst + i0);
            int4 db = *(const int4*)(dst + i0 + 4);
            int p0 = atomicAdd(&g_deg[da.x], 1);
            int p1 = atomicAdd(&g_deg[da.y], 1);
            int p2 = atomicAdd(&g_deg[da.z], 1);
            int p3 = atomicAdd(&g_deg[da.w], 1);
            int p4 = atomicAdd(&g_deg[db.x], 1);
            int p5 = atomicAdd(&g_deg[db.y], 1);
            int p6 = atomicAdd(&g_deg[db.z], 1);
            int p7 = atomicAdd(&g_deg[db.w], 1);
            if (p0 < SLOTS) g_col[(size_t)da.x * SLOTS + p0] = sa.x << 4;
            if (p1 < SLOTS) g_col[(size_t)da.y * SLOTS + p1] = sa.y << 4;
            if (p2 < SLOTS) g_col[(size_t)da.z * SLOTS + p2] = sa.z << 4;
            if (p3 < SLOTS) g_col[(size_t)da.w * SLOTS + p3] = sa.w << 4;
            if (p4 < SLOTS) g_col[(size_t)db.x * SLOTS + p4] = sb.x << 4;
            if (p5 < SLOTS) g_col[(size_t)db.y * SLOTS + p5] = sb.y << 4;
            if (p6 < SLOTS) g_col[(size_t)db.z * SLOTS + p6] = sb.z << 4;
            if (p7 < SLOTS) g_col[(size_t)db.w * SLOTS + p7] = sb.w << 4;
        } else {
            for (int i = i0; i < e; i++) {
                int d = dst[i];
                int p = atomicAdd(&g_deg[d], 1);
                if (p < SLOTS) g_col[(size_t)d * SLOTS + p] = src[i] << 4;
            }
        }
    }
}

// ---------------- agg1: 2 nodes/warp (half-warp each), uint2 gathers, unroll 8 ----------------
// + in-half-warp distinct count (match_any on half mask) + norm + relu
__global__ void agg1_kernel(const __half* __restrict__ h,
                            const float* __restrict__ wpan,
                            float* __restrict__ out, int n) {
    int gw = (blockIdx.x * blockDim.x + threadIdx.x) >> 5;
    int lane = threadIdx.x & 31;
    int half = lane >> 4;
    int l16 = lane & 15;
    int node = gw * 2 + half;
    if (node >= n) return;
    unsigned hmask = half ? 0xFFFF0000u : 0x0000FFFFu;

    int deg = g_deg[node];
    if (deg > SLOTS) deg = SLOTS;
    const int* colp = g_col + (size_t)node * SLOTS;
    int nodeS = node << 4;   // scaled self id (uint2-row index)

    // prefetch self row early (overlaps dedup latency)
    const uint2* hb = (const uint2*)h + l16;   // lane-offset base (uint2 granularity)
    uint2 sv = hb[nodeS];

    // ---- distinct in-neighbor count (coalesce semantics), half-warp chunks of 16 ----
    int cnt = 1;  // diagonal
    for (int c0 = 0; c0 < deg; c0 += 16) {
        int idx = c0 + l16;
        int v = (idx < deg) ? colp[idx] : (-1 - lane);  // unique negatives never match
        bool valid = (idx < deg) && (v != nodeS);
        unsigned m = __match_any_sync(hmask, v);
        bool lead = valid && ((m & ((1u << lane) - 1u)) == 0u);
        if (lead && c0 > 0) {
            for (int j = 0; j < c0; j++)
                if (colp[j] == v) { lead = false; break; }
        }
        cnt += __popc(__ballot_sync(hmask, lead));
    }
    float nm = 1.0f / (float)cnt;
    if (l16 == 0) g_norm[node] = nm;

    // ---- gather-reduce: unroll 8 (two int4 index loads), 4-deep HADD2 trees + fp32 add ----
    float ax = 0.f, ay = 0.f, az = 0.f, aw = 0.f;
    int j = 0;
    for (; j + 7 < deg; j += 8) {
        int4 ca = *(const int4*)(colp + j);
        int4 cb = *(const int4*)(colp + j + 4);
        uint2 v0 = hb[ca.x], v1 = hb[ca.y], v2 = hb[ca.z], v3 = hb[ca.w];
        uint2 v4 = hb[cb.x], v5 = hb[cb.y], v6 = hb[cb.z], v7 = hb[cb.w];
        __half2 sa = __hadd2(__hadd2(*(__half2*)&v0.x, *(__half2*)&v1.x),
                             __hadd2(*(__half2*)&v2.x, *(__half2*)&v3.x));
        __half2 sb = __hadd2(__hadd2(*(__half2*)&v0.y, *(__half2*)&v1.y),
                             __hadd2(*(__half2*)&v2.y, *(__half2*)&v3.y));
        __half2 sc = __hadd2(__hadd2(*(__half2*)&v4.x, *(__half2*)&v5.x),
                             __hadd2(*(__half2*)&v6.x, *(__half2*)&v7.x));
        __half2 sd = __hadd2(__hadd2(*(__half2*)&v4.y, *(__half2*)&v5.y),
                             __hadd2(*(__half2*)&v6.y, *(__half2*)&v7.y));
        float2 fa = __half22float2(sa), fb = __half22float2(sb);
        float2 fc = __half22float2(sc), fd = __half22float2(sd);
        ax += fa.x + fc.x; ay += fa.y + fc.y;
        az += fb.x + fd.x; aw += fb.y + fd.y;
    }
    for (; j + 3 < deg; j += 4) {
        int4 c4 = *(const int4*)(colp + j);
        uint2 v0 = hb[c4.x], v1 = hb[c4.y], v2 = hb[c4.z], v3 = hb[c4.w];
        __half2 sa = __hadd2(__hadd2(*(__half2*)&v0.x, *(__half2*)&v1.x),
                             __hadd2(*(__half2*)&v2.x, *(__half2*)&v3.x));
        __half2 sb = __hadd2(__hadd2(*(__half2*)&v0.y, *(__half2*)&v1.y),
                             __hadd2(*(__half2*)&v2.y, *(__half2*)&v3.y));
        float2 fa = __half22float2(sa);
        float2 fb = __half22float2(sb);
        ax += fa.x; ay += fa.y; az += fb.x; aw += fb.y;
    }
    for (; j < deg; j++) {
        uint2 v = hb[colp[j]];
        float2 fa = __half22float2(*(__half2*)&v.x);
        float2 fb = __half22float2(*(__half2*)&v.y);
        ax += fa.x; ay += fa.y; az += fb.x; aw += fb.y;
    }
    float w0 = wpan[0];
    float w01 = w0 * wpan[1];
    float2 ha = __half22float2(*(__half2*)&sv.x);
    float2 hbv = __half22float2(*(__half2*)&sv.y);
    float4 o;
    o.x = fmaxf(nm * (w0 * ha.x + w01 * ax), 0.f);
    o.y = fmaxf(nm * (w0 * ha.y + w01 * ay), 0.f);
    o.z = fmaxf(nm * (w0 * hbv.x + w01 * az), 0.f);
    o.w = fmaxf(nm * (w0 * hbv.y + w01 * aw), 0.f);
    ((float4*)out)[(size_t)node * 16 + l16] = o;
}

// ---------------- layer-2 linear (packed f32x2, 1 thread/row): h2 = fp16( mid @ W2 + b2 ) ----------------
__global__ __launch_bounds__(256) void lin2_kernel(const float* __restrict__ x,
                                                   const float* __restrict__ W,
                                                   const float* __restrict__ b,
                                                   __half* __restrict__ out, int n) {
    __shared__ float Ws[64 * HID];
    __shared__ float bs[HID];
    for (int i = threadIdx.x; i < (64 * HID) / 4; i += blockDim.x)
        ((float4*)Ws)[i] = ((const float4*)W)[i];
    if (threadIdx.x < HID) bs[threadIdx.x] = b[threadIdx.x];
    __syncthreads();

    int row = blockIdx.x * blockDim.x + threadIdx.x;
    if (row >= n) return;

    unsigned long long acc2[32];
#pragma unroll
    for (int c = 0; c < 32; c++) acc2[c] = 0ull;

    const float4* xr = (const float4*)(x + (size_t)row * 64);
#pragma unroll
    for (int k4 = 0; k4 < 16; k4++) {
        float4 xv = xr[k4];
        float xk[4] = {xv.x, xv.y, xv.z, xv.w};
#pragma unroll
        for (int kk = 0; kk < 4; kk++) {
            unsigned long long xp = pack2(xk[kk], xk[kk]);
            const ulonglong2* wr = (const ulonglong2*)(Ws + (k4 * 4 + kk) * HID);
#pragma unroll
            for (int c = 0; c < 16; c++) {
                ulonglong2 w = wr[c];
                acc2[2 * c + 0] = fma2(xp, w.x, acc2[2 * c + 0]);
                acc2[2 * c + 1] = fma2(xp, w.y, acc2[2 * c + 1]);
            }
        }
    }
    __half2 hv[32];
#pragma unroll
    for (int c = 0; c < 32; c++) {
        float2 v = unpack2(acc2[c]);
        hv[c] = __floats2half2_rn(v.x + bs[2 * c], v.y + bs[2 * c + 1]);
    }
    uint4* o = (uint4*)(out + (size_t)row * HID);
#pragma unroll
    for (int c = 0; c < 8; c++) o[c] = ((uint4*)hv)[c];
}

// ---------------- agg2 + pq: 2 nodes/warp, uint2 gathers, unroll 8, width-16 reduce ----------------
__global__ __launch_bounds__(256) void agg2pq_kernel(const __half* __restrict__ h,
                                                     const float* __restrict__ wpan,
                                                     const float* __restrict__ wc, int n) {
    __shared__ float wcs[256];  // wc [128,2]
    for (int i = threadIdx.x; i < 256; i += blockDim.x) wcs[i] = wc[i];
    __syncthreads();

    int gw = (blockIdx.x * blockDim.x + threadIdx.x) >> 5;
    int lane = threadIdx.x & 31;
    int half = lane >> 4;
    int l16 = lane & 15;
    int node = gw * 2 + half;
    if (node >= n) return;
    unsigned hmask = half ? 0xFFFF0000u : 0x0000FFFFu;

    int deg = g_deg[node];
    if (deg > SLOTS) deg = SLOTS;
    const int* colp = g_col + (size_t)node * SLOTS;

    // prefetch self row + norm early (overlap gather latency)
    const uint2* hb = (const uint2*)h + l16;
    uint2 sv = hb[node << 4];
    float nm = g_norm[node];

    float ax = 0.f, ay = 0.f, az = 0.f, aw = 0.f;
    int j = 0;
    for (; j + 7 < deg; j += 8) {
        int4 ca = *(const int4*)(colp + j);
        int4 cb = *(const int4*)(colp + j + 4);
        uint2 v0 = hb[ca.x], v1 = hb[ca.y], v2 = hb[ca.z], v3 = hb[ca.w];
        uint2 v4 = hb[cb.x], v5 = hb[cb.y], v6 = hb[cb.z], v7 = hb[cb.w];
        __half2 sa = __hadd2(__hadd2(*(__half2*)&v0.x, *(__half2*)&v1.x),
                             __hadd2(*(__half2*)&v2.x, *(__half2*)&v3.x));
        __half2 sb = __hadd2(__hadd2(*(__half2*)&v0.y, *(__half2*)&v1.y),
                             __hadd2(*(__half2*)&v2.y, *(__half2*)&v3.y));
        __half2 sc = __hadd2(__hadd2(*(__half2*)&v4.x, *(__half2*)&v5.x),
                             __hadd2(*(__half2*)&v6.x, *(__half2*)&v7.x));
        __half2 sd = __hadd2(__hadd2(*(__half2*)&v4.y, *(__half2*)&v5.y),
                             __hadd2(*(__half2*)&v6.y, *(__half2*)&v7.y));
        float2 fa = __half22float2(sa), fb = __half22float2(sb);
        float2 fc = __half22float2(sc), fd = __half22float2(sd);
        ax += fa.x + fc.x; ay += fa.y + fc.y;
        az += fb.x + fd.x; aw += fb.y + fd.y;
    }
    for (; j + 3 < deg; j += 4) {
        int4 c4 = *(const int4*)(colp + j);
        uint2 v0 = hb[c4.x], v1 = hb[c4.y], v2 = hb[c4.z], v3 = hb[c4.w];
        __half2 sa = __hadd2(__hadd2(*(__half2*)&v0.x, *(__half2*)&v1.x),
                             __hadd2(*(__half2*)&v2.x, *(__half2*)&v3.x));
        __half2 sb = __hadd2(__hadd2(*(__half2*)&v0.y, *(__half2*)&v1.y),
                             __hadd2(*(__half2*)&v2.y, *(__half2*)&v3.y));
        float2 fa = __half22float2(sa);
        float2 fb = __half22float2(sb);
        ax += fa.x; ay += fa.y; az += fb.x; aw += fb.y;
    }
    for (; j < deg; j++) {
        uint2 v = hb[colp[j]];
        float2 fa = __half22float2(*(__half2*)&v.x);
        float2 fb = __half22float2(*(__half2*)&v.y);
        ax += fa.x; ay += fa.y; az += fb.x; aw += fb.y;
    }
    float w0 = wpan[0];
    float w01 = w0 * wpan[1];
    float2 ha = __half22float2(*(__half2*)&sv.x);
    float2 hbv = __half22float2(*(__half2*)&sv.y);
    float o0 = nm * (w0 * ha.x + w01 * ax);   // h_final[4*l16+0]
    float o1 = nm * (w0 * ha.y + w01 * ay);   // h_final[4*l16+1]
    float o2 = nm * (w0 * hbv.x + w01 * az);  // h_final[4*l16+2]
    float o3 = nm * (w0 * hbv.y + w01 * aw);  // h_final[4*l16+3]

    // classifier halves: lane covers cols c=4*l16..4*l16+3
    int cb4 = 4 * l16;
    float p0 = o0 * wcs[(cb4 + 0) * 2] + o1 * wcs[(cb4 + 1) * 2]
             + o2 * wcs[(cb4 + 2) * 2] + o3 * wcs[(cb4 + 3) * 2];
    float p1 = o0 * wcs[(cb4 + 0) * 2 + 1] + o1 * wcs[(cb4 + 1) * 2 + 1]
             + o2 * wcs[(cb4 + 2) * 2 + 1] + o3 * wcs[(cb4 + 3) * 2 + 1];
    float q0 = o0 * wcs[(64 + cb4 + 0) * 2] + o1 * wcs[(64 + cb4 + 1) * 2]
             + o2 * wcs[(64 + cb4 + 2) * 2] + o3 * wcs[(64 + cb4 + 3) * 2];
    float q1 = o0 * wcs[(64 + cb4 + 0) * 2 + 1] + o1 * wcs[(64 + cb4 + 1) * 2 + 1]
             + o2 * wcs[(64 + cb4 + 2) * 2 + 1] + o3 * wcs[(64 + cb4 + 3) * 2 + 1];
#pragma unroll
    for (int off = 8; off > 0; off >>= 1) {
        p0 += __shfl_down_sync(hmask, p0, off, 16);
        p1 += __shfl_down_sync(hmask, p1, off, 16);
        q0 += __shfl_down_sync(hmask, q0, off, 16);
        q1 += __shfl_down_sync(hmask, q1, off, 16);
    }
    if (l16 == 0) g_pq[node] = make_float4(p0, p1, q0, q1);
}

// ---------------- per-edge output (4 edges/thread) ----------------
__global__ void edge_kernel(const int* __restrict__ src,
                            const int* __restrict__ dst,
                            const float* __restrict__ bc,
                            float* __restrict__ out, int e) {
    int i0 = (blockIdx.x * blockDim.x + threadIdx.x) * 4;
    if (i0 >= e) return;
    float b0 = __ldg(&bc[0]), b1 = __ldg(&bc[1]);
    if (i0 + 4 <= e) {
        int4 s4 = *(const int4*)(src + i0);
        int4 d4 = *(const int4*)(dst + i0);
        float4 pa = g_pq[s4.x], qa = g_pq[d4.x];
        float4 pb = g_pq[s4.y], qb = g_pq[d4.y];
        float4 pc = g_pq[s4.z], qc = g_pq[d4.z];
        float4 pd = g_pq[s4.w], qd = g_pq[d4.w];
        float4 o0, o1;
        o0.x = pa.x + qa.z + b0; o0.y = pa.y + qa.w + b1;
        o0.z = pb.x + qb.z + b0; o0.w = pb.y + qb.w + b1;
        o1.x = pc.x + qc.z + b0; o1.y = pc.y + qc.w + b1;
        o1.z = pd.x + qd.z + b0; o1.w = pd.y + qd.w + b1;
        ((float4*)(out + (size_t)i0 * 2))[0] = o0;
        ((float4*)(out + (size_t)i0 * 2))[1] = o1;
    } else {
        for (int i = i0; i < e; i++) {
            float4 ps = g_pq[src[i]];
            float4 qd = g_pq[dst[i]];
            ((float2*)out)[i] = make_float2(ps.x + qd.z + b0, ps.y + qd.w + b1);
        }
    }
}

// ---------------- launch ----------------
extern "C" void kernel_launch(void* const* d_in, const int* in_sizes, int n_in,
                              void* d_out, int out_size) {
    const float* x   = (const float*)d_in[0];
    const int*   ei  = (const int*)d_in[1];
    const float* w1  = (const float*)d_in[2];
    const float* b1  = (const float*)d_in[3];
    const float* p1  = (const float*)d_in[4];  // w1_pan
    const float* w2  = (const float*)d_in[5];
    const float* b2  = (const float*)d_in[6];
    const float* p2  = (const float*)d_in[7];  // w2_pan
    const float* wc  = (const float*)d_in[8];
    const float* bc  = (const float*)d_in[9];
    float* out = (float*)d_out;

    int n = in_sizes[0] / 128;
    int e = in_sizes[1] / 2;
    const int* src = ei;
    const int* dst = ei + e;

    __half* h1 = nullptr; __half* h2 = nullptr; float* mid = nullptr;
    int* degPtr = nullptr;
    cudaGetSymbolAddress((void**)&h1, g_h1);
    cudaGetSymbolAddress((void**)&h2, g_h2);
    cudaGetSymbolAddress((void**)&mid, g_mid);
    cudaGetSymbolAddress((void**)&degPtr, g_deg);

    int nb256 = (n + 255) / 256;
    int ebv4 = (e / 4 + 255) / 256 + 1;       // 4 edges/thread (edge kernel)
    int ebv8 = (e / 8 + 255) / 256 + 1;       // 8 edges/thread (scatter branch)
    int nbLin = (2 * n + 255) / 256;          // half-row lin1 blocks
    int nwarp2 = (n + 1) / 2;                  // 2 nodes per warp
    int aggBlocks = (nwarp2 * 32 + 255) / 256;

    cudaMemsetAsync(degPtr, 0, (size_t)n * sizeof(int));
    fused_lin1_scatter_kernel<<<nbLin + ebv8, 256>>>(x, w1, b1, src, dst, h1, n, e, nbLin);

    agg1_kernel<<<aggBlocks, 256>>>(h1, p1, mid, n);       // agg1 + distinct/norm + relu
    lin2_kernel<<<nb256, 256>>>(mid, w2, b2, h2, n);       // layer-2 lin (1 thr/row)
    agg2pq_kernel<<<aggBlocks, 256>>>(h2, p2, wc, n);      // layer-2 agg + pq
    edge_kernel<<<ebv4, 256>>>(src, dst, bc, out, e);
}